// round 2
// baseline (speedup 1.0000x reference)
#include <cuda_runtime.h>
#include <math.h>

// Problem constants (from reference): N=200000, D=128, E=500000, NUM_REL=200, B=256
// Scratch (device globals — allocation inside kernel_launch is forbidden).
#define MAX_N    262144
#define MAX_REL  1024
#define MAX_B    4096

__device__ float g_p1[MAX_N];    // <node, W[0:D]>    (row term)
__device__ float g_p2[MAX_N];    // <node, W[D:2D]>   (col term)
__device__ float g_ph[MAX_N];    // <node, W[3D:4D]>  (head term)
__device__ float g_pr3[MAX_REL]; // <R, W[2D:3D]>     (rel term)
__device__ float g_pr5[MAX_REL]; // <R, W[4D:5D]>     (query term)
__device__ float g_hq[MAX_B];    // per-batch: head + query + bias

// ---------------------------------------------------------------------------
// Pass 1: node projections. One warp per node row (grid-stride over warps).
// D=128 = 32 lanes x float4 -> 512B coalesced per row. DRAM-bound (~102 MB).
// ---------------------------------------------------------------------------
__global__ void node_proj_kernel(const float4* __restrict__ ne,
                                 const float4* __restrict__ w,  // W as float4[160]
                                 int N) {
    int lane = threadIdx.x & 31;
    int warp0 = (blockIdx.x * blockDim.x + threadIdx.x) >> 5;
    int nwarps = (gridDim.x * blockDim.x) >> 5;

    float4 w1 = __ldg(&w[lane]);        // W[0:128]
    float4 w2 = __ldg(&w[32 + lane]);   // W[128:256]
    float4 w3 = __ldg(&w[96 + lane]);   // W[384:512]

    for (int row = warp0; row < N; row += nwarps) {
        float4 a = ne[(size_t)row * 32 + lane];
        float s1 = a.x*w1.x + a.y*w1.y + a.z*w1.z + a.w*w1.w;
        float s2 = a.x*w2.x + a.y*w2.y + a.z*w2.z + a.w*w2.w;
        float s3 = a.x*w3.x + a.y*w3.y + a.z*w3.z + a.w*w3.w;
        #pragma unroll
        for (int o = 16; o; o >>= 1) {
            s1 += __shfl_xor_sync(0xffffffffu, s1, o);
            s2 += __shfl_xor_sync(0xffffffffu, s2, o);
            s3 += __shfl_xor_sync(0xffffffffu, s3, o);
        }
        if (lane == 0) {
            g_p1[row] = s1;
            g_p2[row] = s2;
            g_ph[row] = s3;
        }
    }
}

// ---------------------------------------------------------------------------
// Pass 2: relation projections (NUM_REL=200, tiny).
// ---------------------------------------------------------------------------
__global__ void rel_proj_kernel(const float4* __restrict__ R,
                                const float4* __restrict__ w,
                                int NUM_REL) {
    int warp = (blockIdx.x * blockDim.x + threadIdx.x) >> 5;
    int lane = threadIdx.x & 31;
    if (warp >= NUM_REL) return;

    float4 a  = R[(size_t)warp * 32 + lane];
    float4 w3 = __ldg(&w[64 + lane]);    // W[256:384]
    float4 w5 = __ldg(&w[128 + lane]);   // W[512:640]

    float s3 = a.x*w3.x + a.y*w3.y + a.z*w3.z + a.w*w3.w;
    float s5 = a.x*w5.x + a.y*w5.y + a.z*w5.z + a.w*w5.w;
    #pragma unroll
    for (int o = 16; o; o >>= 1) {
        s3 += __shfl_xor_sync(0xffffffffu, s3, o);
        s5 += __shfl_xor_sync(0xffffffffu, s5, o);
    }
    if (lane == 0) {
        g_pr3[warp] = s3;
        g_pr5[warp] = s5;
    }
}

// ---------------------------------------------------------------------------
// Pass 3: per-batch head+query scalar (B=256).
// ---------------------------------------------------------------------------
__global__ void batch_combine_kernel(const int* __restrict__ h_index,
                                     const int* __restrict__ r_index,
                                     const float* __restrict__ bvec,
                                     int B) {
    int i = blockIdx.x * blockDim.x + threadIdx.x;
    if (i >= B) return;
    g_hq[i] = g_ph[h_index[i]] + g_pr5[r_index[i]] + bvec[0];
}

// ---------------------------------------------------------------------------
// Pass 4: per-edge gate. 2 edges per thread for MLP; gathers hit ~800KB
// L2-resident tables; streamed int/eps reads; transcendental tail.
// ---------------------------------------------------------------------------
__global__ void edge_gate_kernel(const int* __restrict__ rows,
                                 const int* __restrict__ cols,
                                 const int* __restrict__ edge_type,
                                 const int* __restrict__ batch_id,
                                 const float* __restrict__ eps_u,
                                 float* __restrict__ out,
                                 int E) {
    int tid = blockIdx.x * blockDim.x + threadIdx.x;
    int stride = gridDim.x * blockDim.x;
    for (int e = tid; e < E; e += stride) {
        int r  = rows[e];
        int c  = cols[e];
        int t  = edge_type[e];
        int bb = batch_id[e];
        float u = eps_u[e];

        float s = g_p1[r] + g_p2[c] + g_pr3[t] + g_hq[bb];

        // eps = (2*BIAS - 1)*u + (1 - BIAS), BIAS = 1e-4
        float eps = fmaf(-0.9998f, u, 0.9999f);
        // gate = (log(eps) - log1p(-eps) + s) / TEMP, TEMP = 5
        float g = (logf(eps) - log1pf(-eps) + s) * 0.2f;
        out[e] = 1.0f / (1.0f + expf(-g));
    }
}

extern "C" void kernel_launch(void* const* d_in, const int* in_sizes, int n_in,
                              void* d_out, int out_size) {
    const float* node_embeds = (const float*)d_in[0];  // (N, 128)
    const float* R           = (const float*)d_in[1];  // (NUM_REL, 128)
    const float* W           = (const float*)d_in[2];  // (640, 1)
    const float* b           = (const float*)d_in[3];  // (1,)
    const float* eps_u       = (const float*)d_in[4];  // (E, 1)
    const int*   edge_index  = (const int*)d_in[5];    // (2, E) int32
    const int*   edge_type   = (const int*)d_in[6];    // (E,)
    const int*   batch_id    = (const int*)d_in[7];    // (E,)
    const int*   h_index     = (const int*)d_in[8];    // (B,)
    const int*   r_index     = (const int*)d_in[9];    // (B,)
    float* out = (float*)d_out;

    const int D = 128;
    int N       = in_sizes[0] / D;
    int NUM_REL = in_sizes[1] / D;
    int E       = in_sizes[4];
    int B       = in_sizes[8];

    const float4* ne4 = (const float4*)node_embeds;
    const float4* R4  = (const float4*)R;
    const float4* W4  = (const float4*)W;

    // Pass 1: node projections. 256 thr = 8 warps/block; enough blocks for
    // full occupancy, grid-stride covers all rows.
    {
        int threads = 256;
        int warps_per_block = threads / 32;
        int blocks = (N + warps_per_block - 1) / warps_per_block;
        if (blocks > 4096) blocks = 4096;
        node_proj_kernel<<<blocks, threads>>>(ne4, W4, N);
    }
    // Pass 2: relation projections
    {
        int threads = 256;
        int blocks = (NUM_REL * 32 + threads - 1) / threads;
        rel_proj_kernel<<<blocks, threads>>>(R4, W4, NUM_REL);
    }
    // Pass 3: per-batch combine
    {
        int threads = 256;
        int blocks = (B + threads - 1) / threads;
        batch_combine_kernel<<<blocks, threads>>>(h_index, r_index, b, B);
    }
    // Pass 4: edge gate (2 edges/thread)
    {
        int threads = 256;
        int blocks = (E / 2 + threads - 1) / threads;
        edge_gate_kernel<<<blocks, threads>>>(edge_index, edge_index + E,
                                              edge_type, batch_id, eps_u, out, E);
    }
}